// round 11
// baseline (speedup 1.0000x reference)
#include <cuda_runtime.h>
#include <cuda_bf16.h>
#include <cstdint>

#define N_NODES 100000
#define N_EDGES 1600000
#define D_HID 64
#define NEG_SLOPE 0.2f
#define MAXDEG 64     // P(Poisson(16) > 64) astronomically small; clamp guards corruption
#define NSPLIT 50048  // node split for pipelining (multiple of 128)

// ------------------------- scratch (static device memory) -------------------
__device__ float g_xl [(size_t)N_NODES * D_HID];
__device__ float g_xr [(size_t)N_NODES * D_HID];
__device__ float g_xl2[(size_t)N_NODES * D_HID];   // layer-2 transform (double buffer)
__device__ float g_xr2[(size_t)N_NODES * D_HID];
__device__ float g_h [(size_t)N_NODES * D_HID];
__device__ int   g_count[N_NODES];
__device__ int2  g_edge[(size_t)N_NODES * MAXDEG]; // direct-scatter bins
__device__ float g_mean[1];                         // raw SUM of ea (divide in GAT)

__device__ __forceinline__ uint32_t f2tf32(float f) {
    uint32_t r;
    asm("cvt.rna.tf32.f32 %0, %1;" : "=r"(r) : "f"(f));
    return r;
}

__device__ __forceinline__ void cp16(void* sdst, const void* gsrc, int szbytes) {
    uint32_t s = (uint32_t)__cvta_generic_to_shared(sdst);
    asm volatile("cp.async.cg.shared.global [%0], [%1], 16, %2;\n"
                 :: "r"(s), "l"(gsrc), "r"(szbytes));
}
__device__ __forceinline__ void cp_commit() {
    asm volatile("cp.async.commit_group;\n");
}
template <int N>
__device__ __forceinline__ void cp_wait() {
    asm volatile("cp.async.wait_group %0;\n" :: "n"(N));
}

// ---------------------- CSR build: zero + direct scatter ---------------------
__global__ void k_zero() {
    int i = blockIdx.x * blockDim.x + threadIdx.x;
    if (i < N_NODES) g_count[i] = 0;
    if (i == 0) g_mean[0] = 0.f;
}

__global__ void k_scatter_mean(const int* __restrict__ src, const int* __restrict__ dst,
                               const float* __restrict__ ea) {
    __shared__ float s[256];
    int e = blockIdx.x * 256 + threadIdx.x;
    float a = 0.f;
    if (e < N_EDGES) {
        int d = dst[e];
        a = ea[e];
        int slot = atomicAdd(&g_count[d], 1);
        if (slot < MAXDEG)
            g_edge[((size_t)d << 6) + slot] = make_int2(src[e], __float_as_int(a));
    }
    s[threadIdx.x] = a;
    __syncthreads();
    for (int o = 128; o > 0; o >>= 1) {
        if (threadIdx.x < o) s[threadIdx.x] += s[threadIdx.x + o];
        __syncthreads();
    }
    if (threadIdx.x == 0) atomicAdd(&g_mean[0], s[0]);
}

// --------------- dual GEMM (TF32 tensor cores, cp.async 2-stage) ------------
#define AS_S 36   // As[m][k] stride (words)
#define BS_S 136  // Bs[k][n] stride (words)
#define AS_SZ (128 * AS_S)
#define BS_SZ (32 * BS_S)
#define GEMM_SMEM ((2 * AS_SZ + 2 * BS_SZ) * 4)

__global__ void __launch_bounds__(256)
k_gemm_tf32(const float* __restrict__ X, int M, int K,
            const float* __restrict__ Wl, const float* __restrict__ bl,
            const float* __restrict__ Wr, const float* __restrict__ br,
            float* __restrict__ xl, float* __restrict__ xr) {
    extern __shared__ float sm[];
    float* Asb = sm;                 // 2 stages of AS_SZ
    float* Bsb = sm + 2 * AS_SZ;     // 2 stages of BS_SZ

    const int tid  = threadIdx.x;
    const int lane = tid & 31;
    const int wid  = tid >> 5;
    const int wm   = (wid & 1) * 64;     // warp m offset
    const int wn   = (wid >> 1) * 32;    // warp n offset
    const int g    = lane >> 2;          // group id
    const int tig  = lane & 3;           // thread in group
    const int m0   = blockIdx.x * 128;

    const int ntiles = (K + 31) / 32;

    auto load_tile = [&](int st, int k0) {
        float* As = Asb + st * AS_SZ;
        float* Bs = Bsb + st * BS_SZ;
#pragma unroll
        for (int it = 0; it < 4; it++) {
            int flat = it * 256 + tid;
            int row = flat >> 3, c4 = flat & 7;
            int grow = m0 + row, gk = k0 + c4 * 4;
            bool ok = (grow < M) && (gk + 4 <= K);
            const float* gp = ok ? (X + (size_t)grow * K + gk) : X;
            cp16(&As[row * AS_S + c4 * 4], gp, ok ? 16 : 0);
        }
#pragma unroll
        for (int it = 0; it < 4; it++) {
            int flat = it * 256 + tid;
            int k = flat >> 5, c4 = flat & 31;
            int gk = k0 + k;
            bool ok = (gk < K);
            const float* gp;
            if (c4 < 16) gp = ok ? (Wl + (size_t)gk * 64 + c4 * 4) : Wl;
            else         gp = ok ? (Wr + (size_t)gk * 64 + (c4 - 16) * 4) : Wr;
            cp16(&Bs[k * BS_S + c4 * 4], gp, ok ? 16 : 0);
        }
        cp_commit();
    };

    float acc[4][4][4];
#pragma unroll
    for (int i = 0; i < 4; i++)
#pragma unroll
        for (int j = 0; j < 4; j++)
#pragma unroll
            for (int r = 0; r < 4; r++) acc[i][j][r] = 0.f;

    load_tile(0, 0);

    for (int kt = 0; kt < ntiles; kt++) {
        int cur = kt & 1;
        if (kt + 1 < ntiles) {
            load_tile(cur ^ 1, (kt + 1) * 32);
            cp_wait<1>();
        } else {
            cp_wait<0>();
        }
        __syncthreads();

        const float* As = Asb + cur * AS_SZ;
        const float* Bs = Bsb + cur * BS_SZ;
#pragma unroll
        for (int kk = 0; kk < 32; kk += 8) {
            uint32_t a[4][4], b[4][2];
#pragma unroll
            for (int mt = 0; mt < 4; mt++) {
                int mr = wm + mt * 16;
                a[mt][0] = f2tf32(As[(mr + g)     * AS_S + kk + tig]);
                a[mt][1] = f2tf32(As[(mr + g + 8) * AS_S + kk + tig]);
                a[mt][2] = f2tf32(As[(mr + g)     * AS_S + kk + tig + 4]);
                a[mt][3] = f2tf32(As[(mr + g + 8) * AS_S + kk + tig + 4]);
            }
#pragma unroll
            for (int nt = 0; nt < 4; nt++) {
                int nc = wn + nt * 8 + g;
                b[nt][0] = f2tf32(Bs[(kk + tig)     * BS_S + nc]);
                b[nt][1] = f2tf32(Bs[(kk + tig + 4) * BS_S + nc]);
            }
#pragma unroll
            for (int mt = 0; mt < 4; mt++)
#pragma unroll
                for (int nt = 0; nt < 4; nt++) {
                    asm volatile(
                        "mma.sync.aligned.m16n8k8.row.col.f32.tf32.tf32.f32 "
                        "{%0,%1,%2,%3},{%4,%5,%6,%7},{%8,%9},{%0,%1,%2,%3};\n"
                        : "+f"(acc[mt][nt][0]), "+f"(acc[mt][nt][1]),
                          "+f"(acc[mt][nt][2]), "+f"(acc[mt][nt][3])
                        : "r"(a[mt][0]), "r"(a[mt][1]), "r"(a[mt][2]), "r"(a[mt][3]),
                          "r"(b[nt][0]), "r"(b[nt][1]));
                }
        }
        __syncthreads();
    }

    // ---- epilogue: add bias, split into xl / xr ----
#pragma unroll
    for (int nt = 0; nt < 4; nt++) {
        int c = wn + nt * 8 + 2 * tig;   // column pair c, c+1
        float2 bv;
        float* dstbase;
        if (c < 64) { bv = make_float2(bl[c], bl[c + 1]); dstbase = xl; }
        else        { bv = make_float2(br[c - 64], br[c - 63]); dstbase = xr; }
        int cc = (c < 64) ? c : c - 64;
#pragma unroll
        for (int mt = 0; mt < 4; mt++) {
            int r0 = m0 + wm + mt * 16 + g;
            if (r0 < M)
                *(float2*)(dstbase + (size_t)r0 * 64 + cc) =
                    make_float2(acc[mt][nt][0] + bv.x, acc[mt][nt][1] + bv.y);
            int r1 = r0 + 8;
            if (r1 < M)
                *(float2*)(dstbase + (size_t)r1 * 64 + cc) =
                    make_float2(acc[mt][nt][2] + bv.x, acc[mt][nt][3] + bv.y);
        }
    }
}

// --------------- GATv2: warp per node, folded lrelu, 32-bit addressing ------
// att·lrelu(z) == (0.6att)·z + (0.4att)·|z|  (exact; fabs is free FFMA modifier)
__global__ void __launch_bounds__(64)
k_gat(const float* __restrict__ xl, const float* __restrict__ xr,
      const float* __restrict__ We, const float* __restrict__ att,
      const float* __restrict__ bias, float* __restrict__ out,
      int n0, int ncnt) {
    int widx = (blockIdx.x * blockDim.x + threadIdx.x) >> 5;
    int lane = threadIdx.x & 31;
    if (widx >= ncnt) return;
    int n = n0 + widx;

    const unsigned loff = (unsigned)(lane << 3);     // byte offset within row
    const char* xlb = (const char*)xl;

    float2 Wev  = *(const float2*)(We  + 2 * lane);
    float2 attv = *(const float2*)(att + 2 * lane);
    float2 xrv  = *(const float2*)((const char*)xr + (((unsigned)n) << 8) + loff);
    float2 xls0 = *(const float2*)(xlb + (((unsigned)n) << 8) + loff);  // self
    float ca0 = 0.6f * attv.x, ca1 = 0.6f * attv.y;
    float cb0 = 0.4f * attv.x, cb1 = 0.4f * attv.y;
    float mea = g_mean[0] * (1.f / (float)N_EDGES);

    // self-loop (ea = mean)
    float z0 = fmaf(mea, Wev.x, xrv.x + xls0.x);
    float z1 = fmaf(mea, Wev.y, xrv.y + xls0.y);
    float p = fmaf(cb0, fabsf(z0), ca0 * z0);
    p = fmaf(ca1, z1, p);
    p = fmaf(cb1, fabsf(z1), p);
#pragma unroll
    for (int o = 16; o; o >>= 1) p += __shfl_xor_sync(0xffffffffu, p, o);
    float ws = __expf(p);

    float den  = ws;
    float acc0 = xls0.x * ws;
    float acc1 = xls0.y * ws;

    const int2* ep = g_edge + ((size_t)n << 6);
    int cnt = g_count[n];
    if (cnt > MAXDEG) cnt = MAXDEG;
    int e = 0;

    for (; e + 4 <= cnt; e += 4) {
        int4 ed01 = *(const int4*)(ep + e);      // (src0,ea0,src1,ea1)
        int4 ed23 = *(const int4*)(ep + e + 2);  // (src2,ea2,src3,ea3)
        int   srcs[4] = { ed01.x, ed01.z, ed23.x, ed23.z };
        float eav[4]  = { __int_as_float(ed01.y), __int_as_float(ed01.w),
                          __int_as_float(ed23.y), __int_as_float(ed23.w) };
        float2 v[4];
        float pp[4];
#pragma unroll
        for (int j = 0; j < 4; j++)
            v[j] = *(const float2*)(xlb + (((unsigned)srcs[j]) << 8) + loff);
#pragma unroll
        for (int j = 0; j < 4; j++) {
            float za = fmaf(eav[j], Wev.x, xrv.x + v[j].x);
            float zb = fmaf(eav[j], Wev.y, xrv.y + v[j].y);
            float q = fmaf(cb0, fabsf(za), ca0 * za);
            q = fmaf(ca1, zb, q);
            pp[j] = fmaf(cb1, fabsf(zb), q);
        }
        // butterfly-merge: 4 warp sums in 9 shfls
        float a0 = pp[0] + __shfl_xor_sync(0xffffffffu, pp[0], 16);
        float a1 = pp[1] + __shfl_xor_sync(0xffffffffu, pp[1], 16);
        float a2 = pp[2] + __shfl_xor_sync(0xffffffffu, pp[2], 16);
        float a3 = pp[3] + __shfl_xor_sync(0xffffffffu, pp[3], 16);
        float c01 = (lane & 16) ? a1 : a0;
        float c23 = (lane & 16) ? a3 : a2;
        c01 += __shfl_xor_sync(0xffffffffu, c01, 8);
        c23 += __shfl_xor_sync(0xffffffffu, c23, 8);
        float d = (lane & 8) ? c23 : c01;
        d += __shfl_xor_sync(0xffffffffu, d, 4);
        d += __shfl_xor_sync(0xffffffffu, d, 2);
        d += __shfl_xor_sync(0xffffffffu, d, 1);
        float w = __expf(d);        // ONE exp for all 4 edges
        float w0 = __shfl_sync(0xffffffffu, w, 0);
        float w2 = __shfl_sync(0xffffffffu, w, 8);
        float w1 = __shfl_sync(0xffffffffu, w, 16);
        float w3 = __shfl_sync(0xffffffffu, w, 24);

        den += ((w0 + w1) + (w2 + w3));
        acc0 = fmaxf(fmaxf(acc0, v[0].x * w0),
                     fmaxf(fmaxf(v[1].x * w1, v[2].x * w2), v[3].x * w3));
        acc1 = fmaxf(fmaxf(acc1, v[0].y * w0),
                     fmaxf(fmaxf(v[1].y * w1, v[2].y * w2), v[3].y * w3));
    }

    for (; e < cnt; ++e) {
        int2 ed = ep[e];
        float eav = __int_as_float(ed.y);
        float2 v = *(const float2*)(xlb + (((unsigned)ed.x) << 8) + loff);
        float za = fmaf(eav, Wev.x, xrv.x + v.x);
        float zb = fmaf(eav, Wev.y, xrv.y + v.y);
        float q = fmaf(cb0, fabsf(za), ca0 * za);
        q = fmaf(ca1, zb, q);
        q = fmaf(cb1, fabsf(zb), q);
#pragma unroll
        for (int o = 16; o; o >>= 1) q += __shfl_xor_sync(0xffffffffu, q, o);
        float w = __expf(q);
        den += w;
        acc0 = fmaxf(acc0, v.x * w);
        acc1 = fmaxf(acc1, v.y * w);
    }

    float inv = 1.f / den;
    float2 bv = *(const float2*)(bias + 2 * lane);
    float o0 = fmaxf(acc0 * inv + bv.x, 0.f);     // +bias, fused relu
    float o1 = fmaxf(acc1 * inv + bv.y, 0.f);
    *(float2*)(out + (size_t)n * 64 + 2 * lane) = make_float2(o0, o1);
}

// --------------- MLP head via TF32 MMA: out = relu(h@W3+b3)@W4 + b4 ---------
#define MAS_S 68
#define MBS_S 72
#define MLP_SMEM ((128 * MAS_S + 64 * MBS_S + 128) * 4)

__global__ void __launch_bounds__(256)
k_mlp_mma(const float* __restrict__ H, int M, const float* __restrict__ W3,
          const float* __restrict__ b3, const float* __restrict__ W4,
          const float* __restrict__ b4, float* __restrict__ out) {
    extern __shared__ float sm[];
    float* As = sm;                       // [128][MAS_S]
    float* Bs = sm + 128 * MAS_S;         // [64][MBS_S]
    float* Os = Bs + 64 * MBS_S;          // [128] row accumulators

    const int tid  = threadIdx.x;
    const int lane = tid & 31;
    const int wid  = tid >> 5;
    const int wm   = (wid & 1) * 64;
    const int wn   = (wid >> 1) * 16;
    const int g    = lane >> 2;
    const int tig  = lane & 3;
    const int m0   = blockIdx.x * 128;

#pragma unroll
    for (int it = 0; it < 8; it++) {
        int flat = it * 256 + tid;        // 2048 float4 slots
        int row = flat >> 4, c4 = flat & 15;
        int grow = m0 + row;
        float4 v = make_float4(0.f, 0.f, 0.f, 0.f);
        if (grow < M)
            v = *(const float4*)(H + (size_t)grow * 64 + c4 * 4);
        float* p = &As[row * MAS_S + c4 * 4];
        p[0] = v.x; p[1] = v.y; p[2] = v.z; p[3] = v.w;
    }
#pragma unroll
    for (int it = 0; it < 4; it++) {
        int flat = it * 256 + tid;        // 1024 float4 slots
        int k = flat >> 4, c4 = flat & 15;
        float4 v = *(const float4*)(W3 + (size_t)k * 64 + c4 * 4);
        float* p = &Bs[k * MBS_S + c4 * 4];
        p[0] = v.x; p[1] = v.y; p[2] = v.z; p[3] = v.w;
    }
    if (tid < 128) Os[tid] = 0.f;
    __syncthreads();

    float acc[4][2][4];
#pragma unroll
    for (int i = 0; i < 4; i++)
#pragma unroll
        for (int j = 0; j < 2; j++)
#pragma unroll
            for (int r = 0; r < 4; r++) acc[i][j][r] = 0.f;

#pragma unroll
    for (int kk = 0; kk < 64; kk += 8) {
        uint32_t a[4][4], b[2][2];
#pragma unroll
        for (int mt = 0; mt < 4; mt++) {
            int mr = wm + mt * 16;
            a[mt][0] = f2tf32(As[(mr + g)     * MAS_S + kk + tig]);
            a[mt][1] = f2tf32(As[(mr + g + 8) * MAS_S + kk + tig]);
            a[mt][2] = f2tf32(As[(mr + g)     * MAS_S + kk + tig + 4]);
            a[mt][3] = f2tf32(As[(mr + g + 8) * MAS_S + kk + tig + 4]);
        }
#pragma unroll
        for (int nt = 0; nt < 2; nt++) {
            int nc = wn + nt * 8 + g;
            b[nt][0] = f2tf32(Bs[(kk + tig)     * MBS_S + nc]);
            b[nt][1] = f2tf32(Bs[(kk + tig + 4) * MBS_S + nc]);
        }
#pragma unroll
        for (int mt = 0; mt < 4; mt++)
#pragma unroll
            for (int nt = 0; nt < 2; nt++) {
                asm volatile(
                    "mma.sync.aligned.m16n8k8.row.col.f32.tf32.tf32.f32 "
                    "{%0,%1,%2,%3},{%4,%5,%6,%7},{%8,%9},{%0,%1,%2,%3};\n"
                    : "+f"(acc[mt][nt][0]), "+f"(acc[mt][nt][1]),
                      "+f"(acc[mt][nt][2]), "+f"(acc[mt][nt][3])
                    : "r"(a[mt][0]), "r"(a[mt][1]), "r"(a[mt][2]), "r"(a[mt][3]),
                      "r"(b[nt][0]), "r"(b[nt][1]));
            }
    }

    float pr0[4], pr1[4];
#pragma unroll
    for (int mt = 0; mt < 4; mt++) { pr0[mt] = 0.f; pr1[mt] = 0.f; }
#pragma unroll
    for (int nt = 0; nt < 2; nt++) {
        int c = wn + nt * 8 + 2 * tig;
        float b3a = b3[c], b3b = b3[c + 1];
        float w4a = W4[c], w4b = W4[c + 1];
#pragma unroll
        for (int mt = 0; mt < 4; mt++) {
            pr0[mt] += fmaxf(acc[mt][nt][0] + b3a, 0.f) * w4a
                     + fmaxf(acc[mt][nt][1] + b3b, 0.f) * w4b;
            pr1[mt] += fmaxf(acc[mt][nt][2] + b3a, 0.f) * w4a
                     + fmaxf(acc[mt][nt][3] + b3b, 0.f) * w4b;
        }
    }
#pragma unroll
    for (int mt = 0; mt < 4; mt++) {
        pr0[mt] += __shfl_xor_sync(0xffffffffu, pr0[mt], 1);
        pr0[mt] += __shfl_xor_sync(0xffffffffu, pr0[mt], 2);
        pr1[mt] += __shfl_xor_sync(0xffffffffu, pr1[mt], 1);
        pr1[mt] += __shfl_xor_sync(0xffffffffu, pr1[mt], 2);
        if (tig == 0) {
            atomicAdd(&Os[wm + mt * 16 + g], pr0[mt]);
            atomicAdd(&Os[wm + mt * 16 + g + 8], pr1[mt]);
        }
    }
    __syncthreads();
    if (tid < 128) {
        int row = m0 + tid;
        if (row < M) out[row] = Os[tid] + b4[0];
    }
}

// ------------------------------ launch --------------------------------------
extern "C" void kernel_launch(void* const* d_in, const int* in_sizes, int n_in,
                              void* d_out, int out_size) {
    const float* x       = (const float*)d_in[0];
    const int*   ei      = (const int*)  d_in[1];
    const float* ea      = (const float*)d_in[2];
    const float* l1_Wl   = (const float*)d_in[3];
    const float* l1_bl   = (const float*)d_in[4];
    const float* l1_Wr   = (const float*)d_in[5];
    const float* l1_br   = (const float*)d_in[6];
    const float* l1_We   = (const float*)d_in[7];
    const float* l1_att  = (const float*)d_in[8];
    const float* l1_bias = (const float*)d_in[9];
    const float* l2_Wl   = (const float*)d_in[10];
    const float* l2_bl   = (const float*)d_in[11];
    const float* l2_Wr   = (const float*)d_in[12];
    const float* l2_br   = (const float*)d_in[13];
    const float* l2_We   = (const float*)d_in[14];
    const float* l2_att  = (const float*)d_in[15];
    const float* l2_bias = (const float*)d_in[16];
    const float* W3      = (const float*)d_in[17];
    const float* b3      = (const float*)d_in[18];
    const float* W4      = (const float*)d_in[19];
    const float* b4      = (const float*)d_in[20];

    const int* src = ei;
    const int* dst = ei + N_EDGES;
    float* out = (float*)d_out;

    void *p_xl, *p_xr, *p_xl2, *p_xr2, *p_h;
    cudaGetSymbolAddress(&p_xl,  g_xl);
    cudaGetSymbolAddress(&p_xr,  g_xr);
    cudaGetSymbolAddress(&p_xl2, g_xl2);
    cudaGetSymbolAddress(&p_xr2, g_xr2);
    cudaGetSymbolAddress(&p_h,   g_h);
    float* xl  = (float*)p_xl;
    float* xr  = (float*)p_xr;
    float* xl2 = (float*)p_xl2;
    float* xr2 = (float*)p_xr2;
    float* h   = (float*)p_h;

    cudaFuncSetAttribute(k_gemm_tf32,
                         cudaFuncAttributeMaxDynamicSharedMemorySize, GEMM_SMEM);
    cudaFuncSetAttribute(k_mlp_mma,
                         cudaFuncAttributeMaxDynamicSharedMemorySize, MLP_SMEM);

    const int TB = 256;
    const int nblk_nodes = (N_NODES + TB - 1) / TB;
    const int nblk_edges = (N_EDGES + TB - 1) / TB;
    const int NA = NSPLIT;                 // half A node count (multiple of 128)
    const int NB = N_NODES - NSPLIT;       // half B node count
    const int gatA_blocks = (NA + 1) / 2;  // 2 nodes per 64-thr block
    const int gatB_blocks = (NB + 1) / 2;
    const int gemm1_blocks = (N_NODES + 127) / 128;
    const int gemmA_blocks = NA / 128;
    const int gemmB_blocks = (NB + 127) / 128;

    cudaStream_t s2;
    cudaStreamCreateWithFlags(&s2, cudaStreamNonBlocking);
    cudaEvent_t evFork, evScat, evA1, evG2A, evA2, evM;
    cudaEventCreateWithFlags(&evFork, cudaEventDisableTiming);
    cudaEventCreateWithFlags(&evScat, cudaEventDisableTiming);
    cudaEventCreateWithFlags(&evA1,  cudaEventDisableTiming);
    cudaEventCreateWithFlags(&evG2A, cudaEventDisableTiming);
    cudaEventCreateWithFlags(&evA2,  cudaEventDisableTiming);
    cudaEventCreateWithFlags(&evM,   cudaEventDisableTiming);

    cudaEventRecord(evFork, 0);
    cudaStreamWaitEvent(s2, evFork, 0);

    // s2: edge binning + mean (overlaps GEMM1)
    k_zero<<<nblk_nodes, TB, 0, s2>>>();
    k_scatter_mean<<<nblk_edges, TB, 0, s2>>>(src, dst, ea);
    cudaEventRecord(evScat, s2);

    // s1: layer-1 GEMM
    k_gemm_tf32<<<gemm1_blocks, 256, GEMM_SMEM>>>(x, N_NODES, 264,
                                                  l1_Wl, l1_bl, l1_Wr, l1_br, xl, xr);
    cudaStreamWaitEvent(0, evScat, 0);

    // s1: gat1 half A, then half B; s2: gemm2_A overlaps gat1_B
    k_gat<<<gatA_blocks, 64>>>(xl, xr, l1_We, l1_att, l1_bias, h, 0, NA);
    cudaEventRecord(evA1, 0);
    cudaStreamWaitEvent(s2, evA1, 0);
    k_gemm_tf32<<<gemmA_blocks, 256, GEMM_SMEM, s2>>>(h, NA, 64,
                                                      l2_Wl, l2_bl, l2_Wr, l2_br, xl2, xr2);
    cudaEventRecord(evG2A, s2);

    k_gat<<<gatB_blocks, 64>>>(xl, xr, l1_We, l1_att, l1_bias, h, NA, NB);
    // s1: gemm2_B (rows B of h), writes xl2/xr2 rows B
    k_gemm_tf32<<<gemmB_blocks, 256, GEMM_SMEM>>>(h + (size_t)NA * 64, NB, 64,
                                                  l2_Wl, l2_bl, l2_Wr, l2_br,
                                                  xl2 + (size_t)NA * 64, xr2 + (size_t)NA * 64);
    cudaStreamWaitEvent(0, evG2A, 0);   // gat2 gathers from ALL xl2 rows

    // s1: gat2 half A, then half B; s2: mlp_A overlaps gat2_B
    k_gat<<<gatA_blocks, 64>>>(xl2, xr2, l2_We, l2_att, l2_bias, h, 0, NA);
    cudaEventRecord(evA2, 0);
    cudaStreamWaitEvent(s2, evA2, 0);
    k_mlp_mma<<<gemmA_blocks, 256, MLP_SMEM, s2>>>(h, NA, W3, b3, W4, b4, out);
    cudaEventRecord(evM, s2);

    k_gat<<<gatB_blocks, 64>>>(xl2, xr2, l2_We, l2_att, l2_bias, h, NA, NB);
    k_mlp_mma<<<gemmB_blocks, 256, MLP_SMEM>>>(h + (size_t)NA * 64, NB, W3, b3, W4, b4,
                                               out + NA);
    cudaStreamWaitEvent(0, evM, 0);     // join side stream before capture ends
}